// round 7
// baseline (speedup 1.0000x reference)
#include <cuda_runtime.h>
#include <cstdint>

#define BATCH 16
#define LQ    16384
#define NC    21
#define HID   256
#define HH    128
#define WW    128
#define SEGG  128
#define NSEG  128

// ---------------- constant memory for small params ----------------
__constant__ float c_w2  [NC * HID];
__constant__ float c_tr  [NC * NC];
__constant__ float c_b1  [HID];
__constant__ float c_b2  [NC];
__constant__ float c_st  [NC];
__constant__ float c_en  [NC];

// ---------------- device scratch ----------------
__device__ float         g_emis  [BATCH * LQ * 32];
__device__ float         g_scores[BATCH * LQ * 32];
__device__ unsigned char g_bp    [BATCH * LQ * 32];
__device__ unsigned char g_segmap[BATCH * NSEG * 32];
__device__ unsigned char g_segend[BATCH * NSEG];
__device__ int           g_lasttag[BATCH];

// =====================================================================
// Kernel 1: fused conv1(3x3,3->256)+b+relu -> conv2(1x1,256->21)+b
// =====================================================================
__global__ __launch_bounds__(256) void emis_kernel(
    const float* __restrict__ x,
    const float* __restrict__ w1)
{
    __shared__ float w1s[HID * 27];
    const int tid = threadIdx.x;
    for (int i = tid; i < HID * 27; i += 256) w1s[i] = w1[i];
    __syncthreads();

    const int blk = blockIdx.x;
    const int b   = blk >> 6;
    const int t   = (blk & 63) * 256 + tid;
    const int y   = t >> 7;
    const int xx  = t & 127;

    float patch[27];
#pragma unroll
    for (int ci = 0; ci < 3; ci++)
#pragma unroll
        for (int dy = 0; dy < 3; dy++)
#pragma unroll
            for (int dx = 0; dx < 3; dx++) {
                int yy = y + dy - 1;
                int xi = xx + dx - 1;
                bool ok = (yy >= 0) & (yy < HH) & (xi >= 0) & (xi < WW);
                patch[ci * 9 + dy * 3 + dx] =
                    ok ? x[((b * 3 + ci) * HH + yy) * WW + xi] : 0.0f;
            }

    float emit[NC];
#pragma unroll
    for (int c = 0; c < NC; c++) emit[c] = 0.0f;

#pragma unroll 2
    for (int h = 0; h < HID; h++) {
        float a = 0.0f;
#pragma unroll
        for (int k = 0; k < 27; k++)
            a = __fmaf_rn(w1s[h * 27 + k], patch[k], a);
        a = fmaxf(a + c_b1[h], 0.0f);
#pragma unroll
        for (int c = 0; c < NC; c++)
            emit[c] = __fmaf_rn(c_w2[c * HID + h], a, emit[c]);
    }

    const int base = (b * LQ + t) * 32;
#pragma unroll
    for (int c = 0; c < NC; c++)
        g_emis[base + c] = emit[c] + c_b2[c];
}

// =====================================================================
// Kernel 2: Viterbi forward (values only), 1 warp per batch.
// Optimization: e added ONCE after the max tree. Bit-exact vs the
// reference's elementwise (s+T)+e formulation because fp rounding is
// monotone: max_p fl(fl(s+T)+e) == fl(max_p fl(s+T) + e).
// =====================================================================
__device__ __forceinline__ float fwd_step(float s, float e, const float* Tc)
{
    float v[NC];
#pragma unroll
    for (int p = 0; p < NC; p++) {
        float sp = __shfl_sync(0xffffffffu, s, p);
        v[p] = sp + Tc[p];
    }
#pragma unroll
    for (int st = 1; st < NC; st <<= 1)
#pragma unroll
        for (int i = 0; i + st < NC; i += 2 * st)
            v[i] = fmaxf(v[i], v[i + st]);
    return v[0] + e;
}

__global__ __launch_bounds__(32, 1) void fwd_kernel()
{
    const int b    = blockIdx.x;
    const int lane = threadIdx.x;
    const int nn   = lane < NC ? lane : NC - 1;

    const float* emis = g_emis   + b * LQ * 32;
    float*       S    = g_scores + b * LQ * 32;

    float Tc[NC];
#pragma unroll
    for (int p = 0; p < NC; p++) Tc[p] = c_tr[p * NC + nn];

    float s = emis[nn] + c_st[nn];
    S[lane] = s;

    // peel t = 1..3
#pragma unroll
    for (int t = 1; t < 4; t++) {
        s = fwd_step(s, emis[t * 32 + nn], Tc);
        S[t * 32 + lane] = s;
    }

    // main loop: t = 4 .. LQ-5 in chunks of 4, clean 4-deep prefetch
    float p0 = emis[4 * 32 + nn], p1 = emis[5 * 32 + nn];
    float p2 = emis[6 * 32 + nn], p3 = emis[7 * 32 + nn];

    for (int t = 4; t < LQ - 4; t += 4) {
        float n0 = emis[(t + 4) * 32 + nn];
        float n1 = emis[(t + 5) * 32 + nn];
        float n2 = emis[(t + 6) * 32 + nn];
        float n3 = emis[(t + 7) * 32 + nn];

        s = fwd_step(s, p0, Tc); S[(t + 0) * 32 + lane] = s;
        s = fwd_step(s, p1, Tc); S[(t + 1) * 32 + lane] = s;
        s = fwd_step(s, p2, Tc); S[(t + 2) * 32 + lane] = s;
        s = fwd_step(s, p3, Tc); S[(t + 3) * 32 + lane] = s;

        p0 = n0; p1 = n1; p2 = n2; p3 = n3;
    }

    // tail: t = LQ-4 .. LQ-1 consumes the last prefetch
    {
        const int t = LQ - 4;
        s = fwd_step(s, p0, Tc); S[(t + 0) * 32 + lane] = s;
        s = fwd_step(s, p1, Tc); S[(t + 1) * 32 + lane] = s;
        s = fwd_step(s, p2, Tc); S[(t + 2) * 32 + lane] = s;
        s = fwd_step(s, p3, Tc); S[(t + 3) * 32 + lane] = s;
    }

    // final tag: first-max over lanes 0..20
    float vend = s + c_en[nn];
    __shared__ float vs[32];
    vs[lane] = vend;
    __syncwarp();
    if (lane == 0) {
        float best = vs[0];
        int   bi   = 0;
#pragma unroll
        for (int p = 1; p < NC; p++)
            if (vs[p] > best) { best = vs[p]; bi = p; }
        g_lasttag[b] = bi;
    }
}

// =====================================================================
// Kernel 3: backpointers, parallel over (b, t>=1).
// Elementwise (s+T)+e with strict-> first-win: bit-matches jnp.argmax.
// =====================================================================
__global__ __launch_bounds__(256) void bp_kernel()
{
    const int gid = blockIdx.x * 256 + threadIdx.x;
    const int b = gid >> 14;
    const int t = gid & (LQ - 1);
    if (t == 0) return;

    const float* Sp = g_scores + (b * LQ + (t - 1)) * 32;
    const float* E  = g_emis   + (b * LQ + t) * 32;
    unsigned char* bp = g_bp   + (b * LQ + t) * 32;

    float sv[NC], ev[NC];
#pragma unroll
    for (int p = 0; p < NC; p++) sv[p] = Sp[p];
#pragma unroll
    for (int c = 0; c < NC; c++) ev[c] = E[c];

#pragma unroll 3
    for (int n = 0; n < NC; n++) {
        float best = -3.0e38f;
        int bi = 0;
        float e = ev[n];
#pragma unroll
        for (int p = 0; p < NC; p++) {
            float a = __fmaf_rn(sv[p], 1.0f, c_tr[p * NC + n]);
            float v = __fmaf_rn(a,     1.0f, e);
            if (v > best) { best = v; bi = p; }
        }
        bp[n] = (unsigned char)bi;
    }
}

// =====================================================================
// Kernel 4a: per-segment end->start tag maps
// =====================================================================
__global__ __launch_bounds__(32) void segmap_kernel()
{
    const int b    = blockIdx.x >> 7;
    const int sg   = blockIdx.x & (NSEG - 1);
    const int lo   = sg * SEGG;
    const int lane = threadIdx.x;

    __shared__ unsigned char bps[SEGG][32];
    const unsigned* src = (const unsigned*)(g_bp + (b * LQ + lo) * 32);
    unsigned* dst = (unsigned*)bps;
    for (int i = lane; i < SEGG * 8; i += 32) dst[i] = src[i];
    __syncwarp();

    int tag = lane < NC ? lane : NC - 1;
    for (int r = SEGG - 1; r >= 1; r--) tag = bps[r][tag & 31];
    g_segmap[(b * NSEG + sg) * 32 + lane] = (unsigned char)tag;
}

// =====================================================================
// Kernel 4b: compose maps -> tag at end of every segment
// =====================================================================
__global__ __launch_bounds__(32) void compose_kernel()
{
    const int b    = blockIdx.x;
    const int lane = threadIdx.x;

    __shared__ unsigned char maps[NSEG][32];
    __shared__ unsigned char bnd [NSEG][32];
    __shared__ unsigned char se  [NSEG];

    {
        const unsigned* src = (const unsigned*)(g_segmap + b * NSEG * 32);
        unsigned* dst = (unsigned*)maps;
        for (int i = lane; i < NSEG * 8; i += 32) dst[i] = src[i];
        unsigned* dstb = (unsigned*)bnd;
        const unsigned* gb = (const unsigned*)g_bp;
        for (int i = lane; i < NSEG * 8; i += 32) {
            int s = i >> 3, w = i & 7;
            dstb[i] = gb[(size_t)(b * LQ + s * SEGG) * 8 + w];
        }
    }
    __syncwarp();

    if (lane == 0) {
        int tag = g_lasttag[b] & 31;
        for (int s = NSEG - 1; s >= 0; s--) {
            se[s] = (unsigned char)tag;
            int tstart = maps[s][tag] & 31;
            if (s > 0) tag = bnd[s][tstart] & 31;
        }
    }
    __syncwarp();
    for (int i = lane; i < NSEG; i += 32) g_segend[b * NSEG + i] = se[i];
}

// =====================================================================
// Kernel 4c: re-chase each segment, emit tags as FLOAT
// =====================================================================
__global__ __launch_bounds__(32) void segemit_kernel(float* __restrict__ out)
{
    const int b    = blockIdx.x >> 7;
    const int sg   = blockIdx.x & (NSEG - 1);
    const int lo   = sg * SEGG;
    const int lane = threadIdx.x;

    __shared__ unsigned char bps[SEGG][32];
    __shared__ unsigned char tagbuf[SEGG];
    const unsigned* src = (const unsigned*)(g_bp + (b * LQ + lo) * 32);
    unsigned* dst = (unsigned*)bps;
    for (int i = lane; i < SEGG * 8; i += 32) dst[i] = src[i];
    __syncwarp();

    if (lane == 0) {
        int tag = g_segend[b * NSEG + sg] & 31;
        for (int r = SEGG - 1; r >= 0; r--) {
            tagbuf[r] = (unsigned char)tag;
            if (r > 0) tag = bps[r][tag] & 31;
        }
    }
    __syncwarp();
    for (int i = lane; i < SEGG; i += 32)
        out[b * LQ + lo + i] = (float)tagbuf[i];
}

// =====================================================================
// Host launcher
// =====================================================================
extern "C" void kernel_launch(void* const* d_in, const int* in_sizes, int n_in,
                              void* d_out, int out_size)
{
    const float *x = 0, *w1 = 0, *b1 = 0, *w2 = 0, *tr = 0;
    const float *v21[3] = {0, 0, 0};
    int n21 = 0, xpos = -1;

    int scale = 0;
    for (int i = 0; i < n_in; i++) {
        if (in_sizes[i] == BATCH * 3 * HH * WW)     { scale = 1; break; }
        if (in_sizes[i] == BATCH * 3 * HH * WW * 4) { scale = 4; break; }
    }
    if (scale) {
        for (int i = 0; i < n_in; i++) {
            int sz = in_sizes[i] / scale;
            const float* p = (const float*)d_in[i];
            if      (sz == BATCH * 3 * HH * WW) { x = p; xpos = i; }
            else if (sz == HID * 27)            w1 = p;
            else if (sz == HID)                 b1 = p;
            else if (sz == NC * HID)            w2 = p;
            else if (sz == NC * NC)             tr = p;
            else if (sz == NC && n21 < 3)       v21[n21++] = p;
        }
    }

    const float *b2, *st, *en;
    if (x && w1 && b1 && w2 && tr && n21 == 3) {
        if (xpos == 0) { b2 = v21[0]; st = v21[1]; en = v21[2]; }  // insertion
        else           { b2 = v21[0]; en = v21[1]; st = v21[2]; }  // name-sorted
    } else {
        x  = (const float*)d_in[0];
        w1 = (const float*)d_in[1];
        b1 = (const float*)d_in[2];
        w2 = (const float*)d_in[3];
        b2 = (const float*)d_in[4];
        st = (const float*)d_in[5];
        en = (const float*)d_in[6];
        tr = (const float*)d_in[7];
    }

    cudaMemcpyToSymbolAsync(c_w2, w2, NC * HID * sizeof(float), 0,
                            cudaMemcpyDeviceToDevice, 0);
    cudaMemcpyToSymbolAsync(c_tr, tr, NC * NC * sizeof(float), 0,
                            cudaMemcpyDeviceToDevice, 0);
    cudaMemcpyToSymbolAsync(c_b1, b1, HID * sizeof(float), 0,
                            cudaMemcpyDeviceToDevice, 0);
    cudaMemcpyToSymbolAsync(c_b2, b2, NC * sizeof(float), 0,
                            cudaMemcpyDeviceToDevice, 0);
    cudaMemcpyToSymbolAsync(c_st, st, NC * sizeof(float), 0,
                            cudaMemcpyDeviceToDevice, 0);
    cudaMemcpyToSymbolAsync(c_en, en, NC * sizeof(float), 0,
                            cudaMemcpyDeviceToDevice, 0);

    float* out = (float*)d_out;

    emis_kernel<<<BATCH * 64, 256>>>(x, w1);
    fwd_kernel<<<BATCH, 32>>>();
    bp_kernel<<<(BATCH * LQ) / 256, 256>>>();
    segmap_kernel<<<BATCH * NSEG, 32>>>();
    compose_kernel<<<BATCH, 32>>>();
    segemit_kernel<<<BATCH * NSEG, 32>>>(out);
}

// round 8
// speedup vs baseline: 1.0838x; 1.0838x over previous
#include <cuda_runtime.h>
#include <cstdint>

#define BATCH 16
#define LQ    16384
#define NC    21
#define HID   256
#define HH    128
#define WW    128
#define SEGG  128
#define NSEG  128

// ---------------- constant memory for small params ----------------
__constant__ float c_w2  [NC * HID];
__constant__ float c_tr  [NC * NC];
__constant__ float c_b1  [HID];
__constant__ float c_b2  [NC];
__constant__ float c_st  [NC];
__constant__ float c_en  [NC];

// ---------------- device scratch ----------------
__device__ float         g_emis  [BATCH * LQ * 32];
__device__ float         g_scores[BATCH * LQ * 32];
__device__ unsigned char g_bp    [BATCH * LQ * 32];
__device__ unsigned char g_segmap[BATCH * NSEG * 32];
__device__ unsigned char g_segend[BATCH * NSEG];
__device__ int           g_lasttag[BATCH];

// =====================================================================
// Kernel 1: fused conv1(3x3,3->256)+b+relu -> conv2(1x1,256->21)+b
// =====================================================================
__global__ __launch_bounds__(256) void emis_kernel(
    const float* __restrict__ x,
    const float* __restrict__ w1)
{
    __shared__ float w1s[HID * 27];
    const int tid = threadIdx.x;
    for (int i = tid; i < HID * 27; i += 256) w1s[i] = w1[i];
    __syncthreads();

    const int blk = blockIdx.x;
    const int b   = blk >> 6;
    const int t   = (blk & 63) * 256 + tid;
    const int y   = t >> 7;
    const int xx  = t & 127;

    float patch[27];
#pragma unroll
    for (int ci = 0; ci < 3; ci++)
#pragma unroll
        for (int dy = 0; dy < 3; dy++)
#pragma unroll
            for (int dx = 0; dx < 3; dx++) {
                int yy = y + dy - 1;
                int xi = xx + dx - 1;
                bool ok = (yy >= 0) & (yy < HH) & (xi >= 0) & (xi < WW);
                patch[ci * 9 + dy * 3 + dx] =
                    ok ? x[((b * 3 + ci) * HH + yy) * WW + xi] : 0.0f;
            }

    float emit[NC];
#pragma unroll
    for (int c = 0; c < NC; c++) emit[c] = 0.0f;

#pragma unroll 2
    for (int h = 0; h < HID; h++) {
        float a = 0.0f;
#pragma unroll
        for (int k = 0; k < 27; k++)
            a = __fmaf_rn(w1s[h * 27 + k], patch[k], a);
        a = fmaxf(a + c_b1[h], 0.0f);
#pragma unroll
        for (int c = 0; c < NC; c++)
            emit[c] = __fmaf_rn(c_w2[c * HID + h], a, emit[c]);
    }

    const int base = (b * LQ + t) * 32;
#pragma unroll
    for (int c = 0; c < NC; c++)
        g_emis[base + c] = emit[c] + c_b2[c];
}

// =====================================================================
// Kernel 2: Viterbi forward, 1 warp per batch.
// SMEM-broadcast formulation: the score vector lives in a double-
// buffered 32-float smem array; each step is
//   BAR.SYNC (3 cyc @ 1 warp) -> 5xLDS.128+1xLDS.32 broadcast ->
//   21x FFMA-imm (adds) -> 20x FMNMX tree -> +e -> STS + STG
// Values bit-exact vs reference: fma(x,1,y)==fl(x+y); tree max ==
// linear max; +e after max == per-element +e (monotone rounding).
// =====================================================================
__device__ __forceinline__ float fwd_step_lds(const float* __restrict__ sb,
                                              float e, const float* Tc)
{
    const float4* q = (const float4*)sb;
    float4 a = q[0], b4 = q[1], c4 = q[2], d4 = q[3], f4 = q[4];
    float  g = sb[20];

    float v[NC];
    v[0]  = __fmaf_rn(a.x,  1.0f, Tc[0]);
    v[1]  = __fmaf_rn(a.y,  1.0f, Tc[1]);
    v[2]  = __fmaf_rn(a.z,  1.0f, Tc[2]);
    v[3]  = __fmaf_rn(a.w,  1.0f, Tc[3]);
    v[4]  = __fmaf_rn(b4.x, 1.0f, Tc[4]);
    v[5]  = __fmaf_rn(b4.y, 1.0f, Tc[5]);
    v[6]  = __fmaf_rn(b4.z, 1.0f, Tc[6]);
    v[7]  = __fmaf_rn(b4.w, 1.0f, Tc[7]);
    v[8]  = __fmaf_rn(c4.x, 1.0f, Tc[8]);
    v[9]  = __fmaf_rn(c4.y, 1.0f, Tc[9]);
    v[10] = __fmaf_rn(c4.z, 1.0f, Tc[10]);
    v[11] = __fmaf_rn(c4.w, 1.0f, Tc[11]);
    v[12] = __fmaf_rn(d4.x, 1.0f, Tc[12]);
    v[13] = __fmaf_rn(d4.y, 1.0f, Tc[13]);
    v[14] = __fmaf_rn(d4.z, 1.0f, Tc[14]);
    v[15] = __fmaf_rn(d4.w, 1.0f, Tc[15]);
    v[16] = __fmaf_rn(f4.x, 1.0f, Tc[16]);
    v[17] = __fmaf_rn(f4.y, 1.0f, Tc[17]);
    v[18] = __fmaf_rn(f4.z, 1.0f, Tc[18]);
    v[19] = __fmaf_rn(f4.w, 1.0f, Tc[19]);
    v[20] = __fmaf_rn(g,    1.0f, Tc[20]);

#pragma unroll
    for (int st = 1; st < NC; st <<= 1)
#pragma unroll
        for (int i = 0; i + st < NC; i += 2 * st)
            v[i] = fmaxf(v[i], v[i + st]);

    return __fmaf_rn(v[0], 1.0f, e);
}

__global__ __launch_bounds__(32) void fwd_kernel()
{
    const int b    = blockIdx.x;
    const int lane = threadIdx.x;
    const int nn   = lane < NC ? lane : NC - 1;

    const float* emis = g_emis   + b * LQ * 32;
    float*       S    = g_scores + b * LQ * 32;

    __shared__ __align__(16) float sb0[32];
    __shared__ __align__(16) float sb1[32];

    float Tc[NC];
#pragma unroll
    for (int p = 0; p < NC; p++) Tc[p] = c_tr[p * NC + nn];

    // t = 0
    float s = __fmaf_rn(emis[nn], 1.0f, c_st[nn]);
    S[lane]   = s;
    sb0[lane] = s;

    // emission prefetch, depth 4
    float e0 = __ldg(&emis[1 * 32 + nn]);
    float e1 = __ldg(&emis[2 * 32 + nn]);
    float e2 = __ldg(&emis[3 * 32 + nn]);
    float e3 = __ldg(&emis[4 * 32 + nn]);

    // pair loop: steps t, t+1 for t = 1, 3, ..., 16381  (16382 steps)
    for (int t = 1; t < LQ - 1; t += 2) {
        int i4 = t + 4 < LQ ? t + 4 : LQ - 1;
        int i5 = t + 5 < LQ ? t + 5 : LQ - 1;
        float n0 = __ldg(&emis[i4 * 32 + nn]);
        float n1 = __ldg(&emis[i5 * 32 + nn]);

        __syncthreads();                       // sb0 ready / sb1 free
        s = fwd_step_lds(sb0, e0, Tc);
        S[t * 32 + lane] = s;
        sb1[lane] = s;

        __syncthreads();                       // sb1 ready / sb0 free
        s = fwd_step_lds(sb1, e1, Tc);
        S[(t + 1) * 32 + lane] = s;
        sb0[lane] = s;

        e0 = e2; e1 = e3; e2 = n0; e3 = n1;
    }

    // final step t = LQ-1 (reads sb0, e0 == E[LQ-1])
    __syncthreads();
    s = fwd_step_lds(sb0, e0, Tc);
    S[(LQ - 1) * 32 + lane] = s;

    // final tag: first-max over lanes 0..20
    float vend = s + c_en[nn];
    __shared__ float vs[32];
    vs[lane] = vend;
    __syncthreads();
    if (lane == 0) {
        float best = vs[0];
        int   bi   = 0;
#pragma unroll
        for (int p = 1; p < NC; p++)
            if (vs[p] > best) { best = vs[p]; bi = p; }
        g_lasttag[b] = bi;
    }
}

// =====================================================================
// Kernel 3: backpointers, parallel over (b, t>=1).
// Elementwise (s+T)+e, strict-> first-win: bit-matches jnp.argmax.
// =====================================================================
__global__ __launch_bounds__(256) void bp_kernel()
{
    const int gid = blockIdx.x * 256 + threadIdx.x;
    const int b = gid >> 14;
    const int t = gid & (LQ - 1);
    if (t == 0) return;

    const float* Sp = g_scores + (b * LQ + (t - 1)) * 32;
    const float* E  = g_emis   + (b * LQ + t) * 32;
    unsigned char* bp = g_bp   + (b * LQ + t) * 32;

    float sv[NC], ev[NC];
#pragma unroll
    for (int p = 0; p < NC; p++) sv[p] = Sp[p];
#pragma unroll
    for (int c = 0; c < NC; c++) ev[c] = E[c];

#pragma unroll 3
    for (int n = 0; n < NC; n++) {
        float best = -3.0e38f;
        int bi = 0;
        float e = ev[n];
#pragma unroll
        for (int p = 0; p < NC; p++) {
            float a = __fmaf_rn(sv[p], 1.0f, c_tr[p * NC + n]);
            float v = __fmaf_rn(a,     1.0f, e);
            if (v > best) { best = v; bi = p; }
        }
        bp[n] = (unsigned char)bi;
    }
}

// =====================================================================
// Kernel 4a: per-segment end->start tag maps
// =====================================================================
__global__ __launch_bounds__(32) void segmap_kernel()
{
    const int b    = blockIdx.x >> 7;
    const int sg   = blockIdx.x & (NSEG - 1);
    const int lo   = sg * SEGG;
    const int lane = threadIdx.x;

    __shared__ unsigned char bps[SEGG][32];
    const unsigned* src = (const unsigned*)(g_bp + (b * LQ + lo) * 32);
    unsigned* dst = (unsigned*)bps;
    for (int i = lane; i < SEGG * 8; i += 32) dst[i] = src[i];
    __syncwarp();

    int tag = lane < NC ? lane : NC - 1;
    for (int r = SEGG - 1; r >= 1; r--) tag = bps[r][tag & 31];
    g_segmap[(b * NSEG + sg) * 32 + lane] = (unsigned char)tag;
}

// =====================================================================
// Kernel 4b: compose maps -> tag at end of every segment
// =====================================================================
__global__ __launch_bounds__(32) void compose_kernel()
{
    const int b    = blockIdx.x;
    const int lane = threadIdx.x;

    __shared__ unsigned char maps[NSEG][32];
    __shared__ unsigned char bnd [NSEG][32];
    __shared__ unsigned char se  [NSEG];

    {
        const unsigned* src = (const unsigned*)(g_segmap + b * NSEG * 32);
        unsigned* dst = (unsigned*)maps;
        for (int i = lane; i < NSEG * 8; i += 32) dst[i] = src[i];
        unsigned* dstb = (unsigned*)bnd;
        const unsigned* gb = (const unsigned*)g_bp;
        for (int i = lane; i < NSEG * 8; i += 32) {
            int s = i >> 3, w = i & 7;
            dstb[i] = gb[(size_t)(b * LQ + s * SEGG) * 8 + w];
        }
    }
    __syncwarp();

    if (lane == 0) {
        int tag = g_lasttag[b] & 31;
        for (int s = NSEG - 1; s >= 0; s--) {
            se[s] = (unsigned char)tag;
            int tstart = maps[s][tag] & 31;
            if (s > 0) tag = bnd[s][tstart] & 31;
        }
    }
    __syncwarp();
    for (int i = lane; i < NSEG; i += 32) g_segend[b * NSEG + i] = se[i];
}

// =====================================================================
// Kernel 4c: re-chase each segment, emit tags as FLOAT
// =====================================================================
__global__ __launch_bounds__(32) void segemit_kernel(float* __restrict__ out)
{
    const int b    = blockIdx.x >> 7;
    const int sg   = blockIdx.x & (NSEG - 1);
    const int lo   = sg * SEGG;
    const int lane = threadIdx.x;

    __shared__ unsigned char bps[SEGG][32];
    __shared__ unsigned char tagbuf[SEGG];
    const unsigned* src = (const unsigned*)(g_bp + (b * LQ + lo) * 32);
    unsigned* dst = (unsigned*)bps;
    for (int i = lane; i < SEGG * 8; i += 32) dst[i] = src[i];
    __syncwarp();

    if (lane == 0) {
        int tag = g_segend[b * NSEG + sg] & 31;
        for (int r = SEGG - 1; r >= 0; r--) {
            tagbuf[r] = (unsigned char)tag;
            if (r > 0) tag = bps[r][tag] & 31;
        }
    }
    __syncwarp();
    for (int i = lane; i < SEGG; i += 32)
        out[b * LQ + lo + i] = (float)tagbuf[i];
}

// =====================================================================
// Host launcher
// =====================================================================
extern "C" void kernel_launch(void* const* d_in, const int* in_sizes, int n_in,
                              void* d_out, int out_size)
{
    const float *x = 0, *w1 = 0, *b1 = 0, *w2 = 0, *tr = 0;
    const float *v21[3] = {0, 0, 0};
    int n21 = 0, xpos = -1;

    int scale = 0;
    for (int i = 0; i < n_in; i++) {
        if (in_sizes[i] == BATCH * 3 * HH * WW)     { scale = 1; break; }
        if (in_sizes[i] == BATCH * 3 * HH * WW * 4) { scale = 4; break; }
    }
    if (scale) {
        for (int i = 0; i < n_in; i++) {
            int sz = in_sizes[i] / scale;
            const float* p = (const float*)d_in[i];
            if      (sz == BATCH * 3 * HH * WW) { x = p; xpos = i; }
            else if (sz == HID * 27)            w1 = p;
            else if (sz == HID)                 b1 = p;
            else if (sz == NC * HID)            w2 = p;
            else if (sz == NC * NC)             tr = p;
            else if (sz == NC && n21 < 3)       v21[n21++] = p;
        }
    }

    const float *b2, *st, *en;
    if (x && w1 && b1 && w2 && tr && n21 == 3) {
        if (xpos == 0) { b2 = v21[0]; st = v21[1]; en = v21[2]; }  // insertion
        else           { b2 = v21[0]; en = v21[1]; st = v21[2]; }  // name-sorted
    } else {
        x  = (const float*)d_in[0];
        w1 = (const float*)d_in[1];
        b1 = (const float*)d_in[2];
        w2 = (const float*)d_in[3];
        b2 = (const float*)d_in[4];
        st = (const float*)d_in[5];
        en = (const float*)d_in[6];
        tr = (const float*)d_in[7];
    }

    cudaMemcpyToSymbolAsync(c_w2, w2, NC * HID * sizeof(float), 0,
                            cudaMemcpyDeviceToDevice, 0);
    cudaMemcpyToSymbolAsync(c_tr, tr, NC * NC * sizeof(float), 0,
                            cudaMemcpyDeviceToDevice, 0);
    cudaMemcpyToSymbolAsync(c_b1, b1, HID * sizeof(float), 0,
                            cudaMemcpyDeviceToDevice, 0);
    cudaMemcpyToSymbolAsync(c_b2, b2, NC * sizeof(float), 0,
                            cudaMemcpyDeviceToDevice, 0);
    cudaMemcpyToSymbolAsync(c_st, st, NC * sizeof(float), 0,
                            cudaMemcpyDeviceToDevice, 0);
    cudaMemcpyToSymbolAsync(c_en, en, NC * sizeof(float), 0,
                            cudaMemcpyDeviceToDevice, 0);

    float* out = (float*)d_out;

    emis_kernel<<<BATCH * 64, 256>>>(x, w1);
    fwd_kernel<<<BATCH, 32>>>();
    bp_kernel<<<(BATCH * LQ) / 256, 256>>>();
    segmap_kernel<<<BATCH * NSEG, 32>>>();
    compose_kernel<<<BATCH, 32>>>();
    segemit_kernel<<<BATCH * NSEG, 32>>>(out);
}

// round 9
// speedup vs baseline: 1.7880x; 1.6497x over previous
#include <cuda_runtime.h>
#include <cstdint>

#define BATCH 16
#define LQ    16384
#define NC    21
#define HID   256
#define HH    128
#define WW    128
#define SEGG  128
#define NSEG  128

// ---------------- constant memory for small params ----------------
__constant__ float c_w2  [NC * HID];
__constant__ float c_tr  [NC * NC];
__constant__ float c_b1  [HID];
__constant__ float c_b2  [NC];
__constant__ float c_st  [NC];
__constant__ float c_en  [NC];

// ---------------- device scratch ----------------
__device__ float         g_emis  [BATCH * LQ * 32];
__device__ float         g_scores[BATCH * LQ * 32];
__device__ unsigned char g_bp    [BATCH * LQ * 32];
__device__ unsigned char g_segmap[BATCH * NSEG * 32];
__device__ unsigned char g_segend[BATCH * NSEG];
__device__ int           g_lasttag[BATCH];

// =====================================================================
// Kernel 1: fused conv1(3x3,3->256)+b+relu -> conv2(1x1,256->21)+b
// =====================================================================
__global__ __launch_bounds__(256) void emis_kernel(
    const float* __restrict__ x,
    const float* __restrict__ w1)
{
    __shared__ float w1s[HID * 27];
    const int tid = threadIdx.x;
    for (int i = tid; i < HID * 27; i += 256) w1s[i] = w1[i];
    __syncthreads();

    const int blk = blockIdx.x;
    const int b   = blk >> 6;
    const int t   = (blk & 63) * 256 + tid;
    const int y   = t >> 7;
    const int xx  = t & 127;

    float patch[27];
#pragma unroll
    for (int ci = 0; ci < 3; ci++)
#pragma unroll
        for (int dy = 0; dy < 3; dy++)
#pragma unroll
            for (int dx = 0; dx < 3; dx++) {
                int yy = y + dy - 1;
                int xi = xx + dx - 1;
                bool ok = (yy >= 0) & (yy < HH) & (xi >= 0) & (xi < WW);
                patch[ci * 9 + dy * 3 + dx] =
                    ok ? x[((b * 3 + ci) * HH + yy) * WW + xi] : 0.0f;
            }

    float emit[NC];
#pragma unroll
    for (int c = 0; c < NC; c++) emit[c] = 0.0f;

#pragma unroll 2
    for (int h = 0; h < HID; h++) {
        float a = 0.0f;
#pragma unroll
        for (int k = 0; k < 27; k++)
            a = __fmaf_rn(w1s[h * 27 + k], patch[k], a);
        a = fmaxf(a + c_b1[h], 0.0f);
#pragma unroll
        for (int c = 0; c < NC; c++)
            emit[c] = __fmaf_rn(c_w2[c * HID + h], a, emit[c]);
    }

    const int base = (b * LQ + t) * 32;
#pragma unroll
    for (int c = 0; c < NC; c++)
        g_emis[base + c] = emit[c] + c_b2[c];
}

// =====================================================================
// Kernel 2: Viterbi forward, 1 warp per batch.
// Score broadcast via double-buffered SMEM + one __syncwarp per step
// (23cyc; vs ~190cyc of SHFL in the R6 version, ~94cyc of BAR in R8).
// Values bit-exact vs reference: FFMA(x,1,y) rounds as x+y; tree max
// == linear max; +e after the max == per-element +e (monotone fl).
// =====================================================================
__device__ __forceinline__ float fwd_step_lds(const float* __restrict__ sb,
                                              float e, const float* Tc)
{
    const float4* q = (const float4*)sb;
    float4 a = q[0], b4 = q[1], c4 = q[2], d4 = q[3], f4 = q[4];
    float  g = sb[20];

    float v[NC];
    v[0]  = __fmaf_rn(a.x,  1.0f, Tc[0]);
    v[1]  = __fmaf_rn(a.y,  1.0f, Tc[1]);
    v[2]  = __fmaf_rn(a.z,  1.0f, Tc[2]);
    v[3]  = __fmaf_rn(a.w,  1.0f, Tc[3]);
    v[4]  = __fmaf_rn(b4.x, 1.0f, Tc[4]);
    v[5]  = __fmaf_rn(b4.y, 1.0f, Tc[5]);
    v[6]  = __fmaf_rn(b4.z, 1.0f, Tc[6]);
    v[7]  = __fmaf_rn(b4.w, 1.0f, Tc[7]);
    v[8]  = __fmaf_rn(c4.x, 1.0f, Tc[8]);
    v[9]  = __fmaf_rn(c4.y, 1.0f, Tc[9]);
    v[10] = __fmaf_rn(c4.z, 1.0f, Tc[10]);
    v[11] = __fmaf_rn(c4.w, 1.0f, Tc[11]);
    v[12] = __fmaf_rn(d4.x, 1.0f, Tc[12]);
    v[13] = __fmaf_rn(d4.y, 1.0f, Tc[13]);
    v[14] = __fmaf_rn(d4.z, 1.0f, Tc[14]);
    v[15] = __fmaf_rn(d4.w, 1.0f, Tc[15]);
    v[16] = __fmaf_rn(f4.x, 1.0f, Tc[16]);
    v[17] = __fmaf_rn(f4.y, 1.0f, Tc[17]);
    v[18] = __fmaf_rn(f4.z, 1.0f, Tc[18]);
    v[19] = __fmaf_rn(f4.w, 1.0f, Tc[19]);
    v[20] = __fmaf_rn(g,    1.0f, Tc[20]);

#pragma unroll
    for (int st = 1; st < NC; st <<= 1)
#pragma unroll
        for (int i = 0; i + st < NC; i += 2 * st)
            v[i] = fmaxf(v[i], v[i + st]);

    return __fmaf_rn(v[0], 1.0f, e);
}

__global__ __launch_bounds__(32) void fwd_kernel()
{
    const int b    = blockIdx.x;
    const int lane = threadIdx.x;
    const int nn   = lane < NC ? lane : NC - 1;

    const float* emis = g_emis   + b * LQ * 32;
    float*       S    = g_scores + b * LQ * 32;

    __shared__ __align__(16) float sb[2][32];

    float Tc[NC];
#pragma unroll
    for (int p = 0; p < NC; p++) Tc[p] = c_tr[p * NC + nn];

    // t = 0: write into sb[0]; step t reads sb[(t-1)&1], writes sb[t&1]
    float s = __fmaf_rn(emis[nn], 1.0f, c_st[nn]);
    S[lane]     = s;
    sb[0][lane] = s;

    // peel t = 1..7 (direct emission loads)
#pragma unroll
    for (int t = 1; t < 8; t++) {
        float e = __ldg(&emis[t * 32 + nn]);
        __syncwarp();
        s = fwd_step_lds(sb[(t - 1) & 1], e, Tc);
        S[t * 32 + lane]   = s;
        sb[t & 1][lane]    = s;
    }

    // 8-deep emission prefetch for the main loop
    float ep[8];
#pragma unroll
    for (int j = 0; j < 8; j++)
        ep[j] = __ldg(&emis[(8 + j) * 32 + nn]);

    // main loop: t = 8 .. 16383 in 2047 chunks of 8
    for (int t = 8; t < LQ; t += 8) {
#pragma unroll
        for (int j = 0; j < 8; j++) {
            __syncwarp();
            s = fwd_step_lds(sb[(t + j - 1) & 1], ep[j], Tc);
            S[(t + j) * 32 + lane]  = s;
            sb[(t + j) & 1][lane]   = s;
        }
        // reload prefetch for next chunk (clamped; harmless on last)
#pragma unroll
        for (int j = 0; j < 8; j++) {
            int tn = t + 8 + j; tn = tn < LQ ? tn : LQ - 1;
            ep[j] = __ldg(&emis[tn * 32 + nn]);
        }
    }

    // final tag: first-max over lanes 0..20
    float vend = s + c_en[nn];
    __shared__ float vs[32];
    vs[lane] = vend;
    __syncwarp();
    if (lane == 0) {
        float best = vs[0];
        int   bi   = 0;
#pragma unroll
        for (int p = 1; p < NC; p++)
            if (vs[p] > best) { best = vs[p]; bi = p; }
        g_lasttag[b] = bi;
    }
}

// =====================================================================
// Kernel 3: backpointers, parallel over (b, t>=1).
// Elementwise (s+T)+e, strict-> first-win: bit-matches jnp.argmax.
// =====================================================================
__global__ __launch_bounds__(256) void bp_kernel()
{
    const int gid = blockIdx.x * 256 + threadIdx.x;
    const int b = gid >> 14;
    const int t = gid & (LQ - 1);
    if (t == 0) return;

    const float* Sp = g_scores + (b * LQ + (t - 1)) * 32;
    const float* E  = g_emis   + (b * LQ + t) * 32;
    unsigned char* bp = g_bp   + (b * LQ + t) * 32;

    float sv[NC], ev[NC];
#pragma unroll
    for (int p = 0; p < NC; p++) sv[p] = Sp[p];
#pragma unroll
    for (int c = 0; c < NC; c++) ev[c] = E[c];

#pragma unroll 3
    for (int n = 0; n < NC; n++) {
        float best = -3.0e38f;
        int bi = 0;
        float e = ev[n];
#pragma unroll
        for (int p = 0; p < NC; p++) {
            float a = __fmaf_rn(sv[p], 1.0f, c_tr[p * NC + n]);
            float v = __fmaf_rn(a,     1.0f, e);
            if (v > best) { best = v; bi = p; }
        }
        bp[n] = (unsigned char)bi;
    }
}

// =====================================================================
// Kernel 4a: per-segment end->start tag maps
// =====================================================================
__global__ __launch_bounds__(32) void segmap_kernel()
{
    const int b    = blockIdx.x >> 7;
    const int sg   = blockIdx.x & (NSEG - 1);
    const int lo   = sg * SEGG;
    const int lane = threadIdx.x;

    __shared__ unsigned char bps[SEGG][32];
    const unsigned* src = (const unsigned*)(g_bp + (b * LQ + lo) * 32);
    unsigned* dst = (unsigned*)bps;
    for (int i = lane; i < SEGG * 8; i += 32) dst[i] = src[i];
    __syncwarp();

    int tag = lane < NC ? lane : NC - 1;
    for (int r = SEGG - 1; r >= 1; r--) tag = bps[r][tag & 31];
    g_segmap[(b * NSEG + sg) * 32 + lane] = (unsigned char)tag;
}

// =====================================================================
// Kernel 4b: compose maps -> tag at end of every segment
// =====================================================================
__global__ __launch_bounds__(32) void compose_kernel()
{
    const int b    = blockIdx.x;
    const int lane = threadIdx.x;

    __shared__ unsigned char maps[NSEG][32];
    __shared__ unsigned char bnd [NSEG][32];
    __shared__ unsigned char se  [NSEG];

    {
        const unsigned* src = (const unsigned*)(g_segmap + b * NSEG * 32);
        unsigned* dst = (unsigned*)maps;
        for (int i = lane; i < NSEG * 8; i += 32) dst[i] = src[i];
        unsigned* dstb = (unsigned*)bnd;
        const unsigned* gb = (const unsigned*)g_bp;
        for (int i = lane; i < NSEG * 8; i += 32) {
            int s = i >> 3, w = i & 7;
            dstb[i] = gb[(size_t)(b * LQ + s * SEGG) * 8 + w];
        }
    }
    __syncwarp();

    if (lane == 0) {
        int tag = g_lasttag[b] & 31;
        for (int s = NSEG - 1; s >= 0; s--) {
            se[s] = (unsigned char)tag;
            int tstart = maps[s][tag] & 31;
            if (s > 0) tag = bnd[s][tstart] & 31;
        }
    }
    __syncwarp();
    for (int i = lane; i < NSEG; i += 32) g_segend[b * NSEG + i] = se[i];
}

// =====================================================================
// Kernel 4c: re-chase each segment, emit tags as FLOAT
// =====================================================================
__global__ __launch_bounds__(32) void segemit_kernel(float* __restrict__ out)
{
    const int b    = blockIdx.x >> 7;
    const int sg   = blockIdx.x & (NSEG - 1);
    const int lo   = sg * SEGG;
    const int lane = threadIdx.x;

    __shared__ unsigned char bps[SEGG][32];
    __shared__ unsigned char tagbuf[SEGG];
    const unsigned* src = (const unsigned*)(g_bp + (b * LQ + lo) * 32);
    unsigned* dst = (unsigned*)bps;
    for (int i = lane; i < SEGG * 8; i += 32) dst[i] = src[i];
    __syncwarp();

    if (lane == 0) {
        int tag = g_segend[b * NSEG + sg] & 31;
        for (int r = SEGG - 1; r >= 0; r--) {
            tagbuf[r] = (unsigned char)tag;
            if (r > 0) tag = bps[r][tag] & 31;
        }
    }
    __syncwarp();
    for (int i = lane; i < SEGG; i += 32)
        out[b * LQ + lo + i] = (float)tagbuf[i];
}

// =====================================================================
// Host launcher
// =====================================================================
extern "C" void kernel_launch(void* const* d_in, const int* in_sizes, int n_in,
                              void* d_out, int out_size)
{
    const float *x = 0, *w1 = 0, *b1 = 0, *w2 = 0, *tr = 0;
    const float *v21[3] = {0, 0, 0};
    int n21 = 0, xpos = -1;

    int scale = 0;
    for (int i = 0; i < n_in; i++) {
        if (in_sizes[i] == BATCH * 3 * HH * WW)     { scale = 1; break; }
        if (in_sizes[i] == BATCH * 3 * HH * WW * 4) { scale = 4; break; }
    }
    if (scale) {
        for (int i = 0; i < n_in; i++) {
            int sz = in_sizes[i] / scale;
            const float* p = (const float*)d_in[i];
            if      (sz == BATCH * 3 * HH * WW) { x = p; xpos = i; }
            else if (sz == HID * 27)            w1 = p;
            else if (sz == HID)                 b1 = p;
            else if (sz == NC * HID)            w2 = p;
            else if (sz == NC * NC)             tr = p;
            else if (sz == NC && n21 < 3)       v21[n21++] = p;
        }
    }

    const float *b2, *st, *en;
    if (x && w1 && b1 && w2 && tr && n21 == 3) {
        if (xpos == 0) { b2 = v21[0]; st = v21[1]; en = v21[2]; }  // insertion
        else           { b2 = v21[0]; en = v21[1]; st = v21[2]; }  // name-sorted
    } else {
        x  = (const float*)d_in[0];
        w1 = (const float*)d_in[1];
        b1 = (const float*)d_in[2];
        w2 = (const float*)d_in[3];
        b2 = (const float*)d_in[4];
        st = (const float*)d_in[5];
        en = (const float*)d_in[6];
        tr = (const float*)d_in[7];
    }

    cudaMemcpyToSymbolAsync(c_w2, w2, NC * HID * sizeof(float), 0,
                            cudaMemcpyDeviceToDevice, 0);
    cudaMemcpyToSymbolAsync(c_tr, tr, NC * NC * sizeof(float), 0,
                            cudaMemcpyDeviceToDevice, 0);
    cudaMemcpyToSymbolAsync(c_b1, b1, HID * sizeof(float), 0,
                            cudaMemcpyDeviceToDevice, 0);
    cudaMemcpyToSymbolAsync(c_b2, b2, NC * sizeof(float), 0,
                            cudaMemcpyDeviceToDevice, 0);
    cudaMemcpyToSymbolAsync(c_st, st, NC * sizeof(float), 0,
                            cudaMemcpyDeviceToDevice, 0);
    cudaMemcpyToSymbolAsync(c_en, en, NC * sizeof(float), 0,
                            cudaMemcpyDeviceToDevice, 0);

    float* out = (float*)d_out;

    emis_kernel<<<BATCH * 64, 256>>>(x, w1);
    fwd_kernel<<<BATCH, 32>>>();
    bp_kernel<<<(BATCH * LQ) / 256, 256>>>();
    segmap_kernel<<<BATCH * NSEG, 32>>>();
    compose_kernel<<<BATCH, 32>>>();
    segemit_kernel<<<BATCH * NSEG, 32>>>(out);
}